// round 13
// baseline (speedup 1.0000x reference)
#include <cuda_runtime.h>
#include <math.h>

#define PATCH    32
#define HP       256
#define WP       256
#define NPATCH   (HP * WP)      // 65536
#define IMG_W    8192
#define NGRID    (NPATCH / 4)   // 16384 CTAs, 4 patches each
#define GROUPS   64             // 64 groups x 256 CTAs
#define GSIZE    256

// ln(0.04 * sqrt(2*pi)) = -2.2999372...
#define LOG_NORM_CONST (-2.2999372199f)

// 4 patch means per CTA; level-2 partials; arrival counters (zero-init).
__device__ float4 g_means4[NGRID];
__device__ float4 g_part2[GROUPS];
__device__ unsigned int g_cnt1[GROUPS];
__device__ unsigned int g_cnt2;

// Release-ordered arrival: orders this CTA's prior global stores before the
// counter bump WITHOUT a gpu-scope membar (no CCTL.IVALL / L1D flush).
__device__ __forceinline__ unsigned int arrive_release(unsigned int* p) {
    unsigned int old;
    asm volatile("atom.release.gpu.global.add.u32 %0, [%1], 1;"
                 : "=r"(old) : "l"(p) : "memory");
    return old;
}

__device__ __forceinline__ void accum_term(float m, float mk,
                                           float& ps, float& ns, float& pc) {
    const float z = (m - 0.34f) * 25.0f;
    const float logpdf = -0.5f * z * z - LOG_NORM_CONST;
    const float pos_t = -logf(expf(logpdf) + 1e-6f);
    if (mk >= 0.5f) { ps += pos_t; pc += 1.0f; }
    else            { ns += m * m; }
}

// Streaming CTA: 4 horizontally-adjacent patches, R2-k1 lean structure.
// Tail = one float4 store + one release atomic. No fence, no exp/log.
__global__ void __launch_bounds__(256, 8)
fused_kernel(const float* __restrict__ x, const float* __restrict__ tmask,
             float* __restrict__ out) {
    const int g   = blockIdx.x;
    const int ph  = g >> 6;              // patch row (64 CTAs per row)
    const int pg  = g & 63;
    const int tid = threadIdx.x;
    const int row = tid >> 3;            // 0..31
    const int q   = tid & 7;             // 0..7

    const size_t base = (size_t)(ph * PATCH + row) * IMG_W + (size_t)pg * 128;
    const float4* p4 = (const float4*)(x + base);

    float s[4];
    #pragma unroll
    for (int k = 0; k < 4; k++) {        // 4 independent loads
        const float4 v = p4[k * 8 + q];
        s[k] = (v.x + v.y) + (v.z + v.w);
    }

    #pragma unroll
    for (int o = 16; o > 0; o >>= 1) {
        #pragma unroll
        for (int k = 0; k < 4; k++)
            s[k] += __shfl_xor_sync(0xffffffffu, s[k], o);
    }

    __shared__ float sm[8][4];
    const int w = tid >> 5;
    const int l = tid & 31;
    if (l == 0) {
        #pragma unroll
        for (int k = 0; k < 4; k++) sm[w][k] = s[k];
    }
    __syncthreads();

    __shared__ bool s_glast;
    if (tid < 32) {
        float v = sm[tid >> 2][tid & 3];   // lane = warp*4 + k
        v += __shfl_xor_sync(0xffffffffu, v, 4);
        v += __shfl_xor_sync(0xffffffffu, v, 8);
        v += __shfl_xor_sync(0xffffffffu, v, 16);
        const float m  = v * (1.0f / (PATCH * PATCH));   // lanes 0..3 valid
        const float m1 = __shfl_sync(0xffffffffu, m, 1);
        const float m2 = __shfl_sync(0xffffffffu, m, 2);
        const float m3 = __shfl_sync(0xffffffffu, m, 3);
        if (tid == 0) {
            g_means4[g] = make_float4(m, m1, m2, m3);
            const unsigned int old = arrive_release(&g_cnt1[g >> 8]);
            s_glast = (old == GSIZE - 1);
        }
    }
    __syncthreads();
    if (!s_glast) return;

    // ---- Group-last CTA (64 total): terms + reduce for 1024 patches ----
    __threadfence();                      // acquire; rare (64 execs)
    const int gid = g >> 8;
    if (tid == 0) g_cnt1[gid] = 0;        // reset for next graph replay

    const float4 mv  = g_means4[gid * GSIZE + tid];
    const float4 mk4 = ((const float4*)tmask)[gid * GSIZE + tid];

    float ps = 0.0f, ns = 0.0f, pc = 0.0f;
    accum_term(mv.x, mk4.x, ps, ns, pc);
    accum_term(mv.y, mk4.y, ps, ns, pc);
    accum_term(mv.z, mk4.z, ps, ns, pc);
    accum_term(mv.w, mk4.w, ps, ns, pc);

    #pragma unroll
    for (int o = 16; o > 0; o >>= 1) {
        ps += __shfl_xor_sync(0xffffffffu, ps, o);
        ns += __shfl_xor_sync(0xffffffffu, ns, o);
        pc += __shfl_xor_sync(0xffffffffu, pc, o);
    }
    __shared__ float3 pr[8];
    if (l == 0) pr[w] = make_float3(ps, ns, pc);
    __syncthreads();

    __shared__ bool s_final;
    if (tid < 8) {
        float3 a = pr[tid];
        float cps = a.x, cns = a.y, cpc = a.z;
        #pragma unroll
        for (int o = 4; o > 0; o >>= 1) {
            cps += __shfl_xor_sync(0xffu, cps, o);
            cns += __shfl_xor_sync(0xffu, cns, o);
            cpc += __shfl_xor_sync(0xffu, cpc, o);
        }
        if (tid == 0) {
            g_part2[gid] = make_float4(cps, cns, cpc, 0.0f);
            const unsigned int old = arrive_release(&g_cnt2);
            s_final = (old == GROUPS - 1);
        }
    }
    __syncthreads();
    if (!s_final) return;

    // ---- Globally-last CTA: fold 64 partials, write scalar ----
    __threadfence();                      // acquire; single exec
    __shared__ float3 fr[2];
    if (tid < 64) {
        const float4 p = g_part2[tid];
        float fps = p.x, fns = p.y, fpc = p.z;
        #pragma unroll
        for (int o = 16; o > 0; o >>= 1) {
            fps += __shfl_xor_sync(0xffffffffu, fps, o);
            fns += __shfl_xor_sync(0xffffffffu, fns, o);
            fpc += __shfl_xor_sync(0xffffffffu, fpc, o);
        }
        if (l == 0) fr[w] = make_float3(fps, fns, fpc);
    }
    __syncthreads();
    if (tid == 0) {
        const float fps = fr[0].x + fr[1].x;
        const float fns = fr[0].y + fr[1].y;
        const float fpc = fr[0].z + fr[1].z;
        const float fnc = (float)NPATCH - fpc;
        out[0] = fps / fpc + fns / fnc;
        g_cnt2 = 0;                       // reset for next graph replay
    }
}

extern "C" void kernel_launch(void* const* d_in, const int* in_sizes, int n_in,
                              void* d_out, int out_size) {
    const float* unet  = (const float*)d_in[0];   // [1,1,8192,8192] fp32
    const float* tmask = (const float*)d_in[1];   // [1,256,256] fp32
    float* out = (float*)d_out;

    fused_kernel<<<NGRID, 256>>>(unet, tmask, out);
}

// round 14
// speedup vs baseline: 1.3343x; 1.3343x over previous
#include <cuda_runtime.h>
#include <math.h>

#define PATCH    32
#define HP       256
#define WP       256
#define NPATCH   (HP * WP)        // 65536
#define IMG_W    8192
#define IMG_W4   (IMG_W / 4)      // 2048 float4 per row
#define PPB      64               // patches per CTA (8 warps x 8 iters)
#define NGRID1   (NPATCH / PPB)   // 1024 CTAs

// ln(0.04 * sqrt(2*pi)) = -2.2999372...
#define LOG_NORM_CONST (-2.2999372199f)

// Per-CTA partials: (pos_sum, neg_sum, pos_count, unused)
__device__ float4 g_part[NGRID1];
__device__ unsigned int g_count;   // zero-initialized; reset by last CTA

// Fused kernel: warp-per-patch streaming reduce + last-CTA finish.
// Final committed configuration (best measured: 43.5us, 79.3% DRAM,
// 6.28 TB/s). Grid 1024 x 256 threads, 8 patches per warp, MLP 8,
// occ-8 register budget, interleaved shfl reduces hidden under memory.
__global__ void __launch_bounds__(256, 8)
fused_kernel(const float* __restrict__ x, const float* __restrict__ tmask,
             float* __restrict__ out) {
    const int tid = threadIdx.x;
    const int w   = tid >> 5;            // warp 0..7
    const int l   = tid & 31;            // lane
    const int p_base = blockIdx.x * PPB; // first patch of this CTA

    __shared__ float means[PPB];

    const int lrow = l >> 3;             // 0..3 base row
    const int lq   = l & 7;              // float4 within 128B row segment

    #pragma unroll
    for (int t = 0; t < 8; t++) {
        const int p  = p_base + t * 8 + w;
        const int ph = p >> 8;
        const int pw = p & 255;
        const float4* p4 = (const float4*)x
                         + (size_t)(ph * PATCH) * IMG_W4 + (size_t)pw * 8;

        float s = 0.0f;
        #pragma unroll
        for (int k = 0; k < 8; k++) {    // 8 independent loads in flight
            const float4 v = __ldcs(&p4[(size_t)(lrow + 4 * k) * IMG_W4 + lq]);
            s += (v.x + v.y) + (v.z + v.w);
        }

        #pragma unroll
        for (int o = 16; o > 0; o >>= 1)
            s += __shfl_xor_sync(0xffffffffu, s, o);

        if (l == 0) means[t * 8 + w] = s * (1.0f / (PATCH * PATCH));
    }
    __syncthreads();

    // Tail: 64 parallel term computations, then block reduce.
    float ps = 0.0f, ns = 0.0f, pc = 0.0f;
    if (tid < PPB) {
        const float mean = means[tid];
        const float z = (mean - 0.34f) * 25.0f;
        const float logpdf = -0.5f * z * z - LOG_NORM_CONST;
        const float pos_t = -logf(expf(logpdf) + 1e-6f);
        const float neg_t = mean * mean;
        const float mk = (tmask[p_base + tid] >= 0.5f) ? 1.0f : 0.0f;
        ps = pos_t * mk;
        ns = neg_t * (1.0f - mk);
        pc = mk;
    }

    if (tid < 64) {
        #pragma unroll
        for (int o = 16; o > 0; o >>= 1) {
            ps += __shfl_xor_sync(0xffffffffu, ps, o);
            ns += __shfl_xor_sync(0xffffffffu, ns, o);
            pc += __shfl_xor_sync(0xffffffffu, pc, o);
        }
    }
    __shared__ float3 pr[2];
    if (tid == 0 || tid == 32) pr[tid >> 5] = make_float3(ps, ns, pc);
    __syncthreads();

    __shared__ bool s_last;
    if (tid == 0) {
        const float3 a = pr[0], b = pr[1];
        g_part[blockIdx.x] = make_float4(a.x + b.x, a.y + b.y, a.z + b.z, 0.0f);
        __threadfence();
        const unsigned int old = atomicAdd(&g_count, 1u);
        s_last = (old == NGRID1 - 1);
    }
    __syncthreads();

    if (!s_last) return;

    // ---- Last CTA: reduce all 1024 partials in fixed order (deterministic) ----
    float fps = 0.0f, fns = 0.0f, fpc = 0.0f;
    #pragma unroll
    for (int k = 0; k < NGRID1 / 256; k++) {      // 4 independent loads
        const float4 p = g_part[tid + k * 256];
        fps += p.x; fns += p.y; fpc += p.z;
    }

    #pragma unroll
    for (int o = 16; o > 0; o >>= 1) {
        fps += __shfl_xor_sync(0xffffffffu, fps, o);
        fns += __shfl_xor_sync(0xffffffffu, fns, o);
        fpc += __shfl_xor_sync(0xffffffffu, fpc, o);
    }

    __shared__ float f_ps[8], f_ns[8], f_pc[8];
    if (l == 0) { f_ps[w] = fps; f_ns[w] = fns; f_pc[w] = fpc; }
    __syncthreads();

    if (tid < 8) {
        fps = f_ps[tid]; fns = f_ns[tid]; fpc = f_pc[tid];
        #pragma unroll
        for (int o = 4; o > 0; o >>= 1) {
            fps += __shfl_xor_sync(0xffu, fps, o);
            fns += __shfl_xor_sync(0xffu, fns, o);
            fpc += __shfl_xor_sync(0xffu, fpc, o);
        }
        if (tid == 0) {
            const float fnc = (float)NPATCH - fpc;
            out[0] = fps / fpc + fns / fnc;
            g_count = 0;                  // reset for next graph replay
        }
    }
}

extern "C" void kernel_launch(void* const* d_in, const int* in_sizes, int n_in,
                              void* d_out, int out_size) {
    const float* unet  = (const float*)d_in[0];   // [1,1,8192,8192] fp32
    const float* tmask = (const float*)d_in[1];   // [1,256,256] fp32
    float* out = (float*)d_out;

    fused_kernel<<<NGRID1, 256>>>(unet, tmask, out);
}